// round 1
// baseline (speedup 1.0000x reference)
#include <cuda_runtime.h>
#include <math.h>

#define BATCH 2
#define SEQ   2048
#define DIM   2048
#define NH    16
#define NKV   4
#define HD    128
#define MROWS (BATCH*SEQ)   /* 4096 */
#define KVDIM (NKV*HD)      /* 512  */

// ---------------- scratch (static device allocations; no cudaMalloc) --------
__device__ float g_q [MROWS*DIM];    // q after proj/norm/rope  [row][h*128+d]
__device__ float g_k [MROWS*KVDIM];  // k after proj/norm/rope  [row][kv*128+d]
__device__ float g_v [MROWS*KVDIM];  // v after proj             [row][kv*128+d]
__device__ float g_ao[MROWS*DIM];    // attention output         [row][h*128+d]

// ---------------- classic 128x128x8 SGEMM, 8x8 microtile ---------------------
// A: MxK row-major, B: KxN row-major, C: MxN row-major. M,N multiples of 128,
// K multiple of 8.
__global__ __launch_bounds__(256) void sgemm128(const float* __restrict__ A,
                                                const float* __restrict__ B,
                                                float* __restrict__ C,
                                                int N, int K) {
    __shared__ float As[8][128];
    __shared__ float Bs[8][128];
    const int bx = blockIdx.x, by = blockIdx.y;
    const int tid = threadIdx.x;
    const int tx = tid & 15, ty = tid >> 4;
    const int a_row = tid >> 1;
    const int a_col = (tid & 1) * 4;
    const int b_row = tid >> 5;
    const int b_col = (tid & 31) * 4;

    const float* Ab = A + (size_t)(by * 128) * K;
    const float* Bb = B + bx * 128;

    float acc[8][8];
#pragma unroll
    for (int i = 0; i < 8; i++)
#pragma unroll
        for (int j = 0; j < 8; j++) acc[i][j] = 0.f;

    for (int k0 = 0; k0 < K; k0 += 8) {
        float4 av = *(const float4*)(Ab + (size_t)a_row * K + k0 + a_col);
        As[a_col + 0][a_row] = av.x;
        As[a_col + 1][a_row] = av.y;
        As[a_col + 2][a_row] = av.z;
        As[a_col + 3][a_row] = av.w;
        *(float4*)&Bs[b_row][b_col] =
            *(const float4*)(Bb + (size_t)(k0 + b_row) * N + b_col);
        __syncthreads();
#pragma unroll
        for (int kk = 0; kk < 8; kk++) {
            float ar[8], br[8];
            *(float4*)(ar)     = *(const float4*)&As[kk][ty * 8];
            *(float4*)(ar + 4) = *(const float4*)&As[kk][ty * 8 + 4];
            *(float4*)(br)     = *(const float4*)&Bs[kk][tx * 8];
            *(float4*)(br + 4) = *(const float4*)&Bs[kk][tx * 8 + 4];
#pragma unroll
            for (int i = 0; i < 8; i++)
#pragma unroll
                for (int j = 0; j < 8; j++)
                    acc[i][j] += ar[i] * br[j];
        }
        __syncthreads();
    }

#pragma unroll
    for (int i = 0; i < 8; i++) {
        float* Crow = C + (size_t)(by * 128 + ty * 8 + i) * N + bx * 128 + tx * 8;
        *(float4*)Crow       = make_float4(acc[i][0], acc[i][1], acc[i][2], acc[i][3]);
        *(float4*)(Crow + 4) = make_float4(acc[i][4], acc[i][5], acc[i][6], acc[i][7]);
    }
}

// ---------------- fused per-head RMSNorm + RoPE (in place) -------------------
// grid: (MROWS, 20). blockIdx.y in [0,16): q head, [16,20): k head. 128 thr.
__global__ __launch_bounds__(128) void normrope(float* __restrict__ q,
                                                float* __restrict__ k,
                                                const float* __restrict__ qw,
                                                const float* __restrict__ kw) {
    const int row = blockIdx.x;          // b*SEQ + s
    const int hy  = blockIdx.y;
    const int d   = threadIdx.x;         // 0..127
    const int s   = row & (SEQ - 1);

    float* p;
    const float* w;
    if (hy < NH) { p = q + (size_t)row * DIM   + hy * HD;        w = qw; }
    else         { p = k + (size_t)row * KVDIM + (hy - NH) * HD; w = kw; }

    float x = p[d];

    // mean of squares over 128
    float v2 = x * x;
#pragma unroll
    for (int off = 16; off > 0; off >>= 1)
        v2 += __shfl_xor_sync(0xffffffffu, v2, off);
    __shared__ float wsum[4];
    const int lane = d & 31, wid = d >> 5;
    if (lane == 0) wsum[wid] = v2;
    __syncthreads();
    float total = wsum[0] + wsum[1] + wsum[2] + wsum[3];
    float rn = rsqrtf(total * (1.0f / 128.0f) + 1e-6f);
    float nx = x * rn * w[d];

    __shared__ float sn[128];
    sn[d] = nx;
    __syncthreads();

    // RoPE: angle computed as fp32 (s * inv_freq) like the reference tables,
    // then accurate double cos/sin on that fp32 angle.
    const int j = d & 63;
    float invf  = (float)exp(-9.210340371976184 * ((double)(2 * j) * (1.0 / 128.0)));
    float theta = (float)s * invf;
    double td = (double)theta;
    float c  = (float)cos(td);
    float si = (float)sin(td);
    float out = (d < 64) ? (nx * c - sn[d + 64] * si)
                         : (nx * c + sn[d - 64] * si);
    p[d] = out;
}

// ---------------- flash attention, fp32, BM=64 BN=64 D=128 -------------------
// grid (SEQ/64, NH, BATCH), 256 threads, dynamic smem.
// smem layout (floats), padded strides for conflict-free LDS:
//   Qs[64][132], Ks[64][132], Vs[64][132], Ps[64][65], redm[64][9], reds[64][9]
#define QKV_STRIDE 132
#define P_STRIDE   65
#define RED_STRIDE 9
#define FLASH_SMEM_FLOATS (3*64*QKV_STRIDE + 64*P_STRIDE + 2*64*RED_STRIDE)

__global__ __launch_bounds__(256) void flash_attn(const float* __restrict__ q,
                                                  const float* __restrict__ k,
                                                  const float* __restrict__ v,
                                                  float* __restrict__ ao) {
    extern __shared__ float sm[];
    float* Qs   = sm;
    float* Ks   = Qs + 64 * QKV_STRIDE;
    float* Vs   = Ks + 64 * QKV_STRIDE;
    float* Ps   = Vs + 64 * QKV_STRIDE;
    float* redm = Ps + 64 * P_STRIDE;
    float* reds = redm + 64 * RED_STRIDE;

    const int qt  = blockIdx.x;   // q tile (0..31)
    const int h   = blockIdx.y;   // q head (0..15)
    const int b   = blockIdx.z;
    const int kv  = h >> 2;       // G = 4
    const int tid = threadIdx.x;

    // thread owns S rows {r0, r1}, S cols [c0, c0+8), O cols [tcol*16, +16)
    const int r0   = tid & 31;
    const int r1   = r0 + 32;
    const int tcol = tid >> 5;    // 0..7
    const int c0   = tcol * 8;

    const float scale = 0.08838834764831843f;  // 128^-0.5

    // load Q tile (pre-scaled)
    const float* qbase = q + ((size_t)(b * SEQ + qt * 64)) * DIM + h * HD;
#pragma unroll
    for (int i = 0; i < 8; i++) {
        int lin = tid + i * 256;        // float4 index among 2048
        int m = lin >> 5, d4 = lin & 31;
        float4 t = *(const float4*)(qbase + (size_t)m * DIM + d4 * 4);
        t.x *= scale; t.y *= scale; t.z *= scale; t.w *= scale;
        *(float4*)(Qs + m * QKV_STRIDE + d4 * 4) = t;
    }

    float mi0 = -1e30f, mi1 = -1e30f, li0 = 0.f, li1 = 0.f;
    float o0[16], o1[16];
#pragma unroll
    for (int i = 0; i < 16; i++) { o0[i] = 0.f; o1[i] = 0.f; }

    const float* kbase = k + (size_t)(b * SEQ) * KVDIM + kv * HD;
    const float* vbase = v + (size_t)(b * SEQ) * KVDIM + kv * HD;

    for (int kt = 0; kt < SEQ / 64; kt++) {
        const float* kb = kbase + (size_t)(kt * 64) * KVDIM;
        const float* vb = vbase + (size_t)(kt * 64) * KVDIM;
#pragma unroll
        for (int i = 0; i < 8; i++) {
            int lin = tid + i * 256;
            int n = lin >> 5, d4 = lin & 31;
            *(float4*)(Ks + n * QKV_STRIDE + d4 * 4) =
                *(const float4*)(kb + (size_t)n * KVDIM + d4 * 4);
            *(float4*)(Vs + n * QKV_STRIDE + d4 * 4) =
                *(const float4*)(vb + (size_t)n * KVDIM + d4 * 4);
        }
        __syncthreads();

        // S = Q K^T for my 2x8 patch
        float acc0[8], acc1[8];
#pragma unroll
        for (int j = 0; j < 8; j++) { acc0[j] = 0.f; acc1[j] = 0.f; }
        const float4* q0p = (const float4*)(Qs + r0 * QKV_STRIDE);
        const float4* q1p = (const float4*)(Qs + r1 * QKV_STRIDE);
#pragma unroll 4
        for (int d4 = 0; d4 < 32; d4++) {
            float4 a0 = q0p[d4], a1 = q1p[d4];
#pragma unroll
            for (int j = 0; j < 8; j++) {
                float4 kk4 = *(const float4*)(Ks + (c0 + j) * QKV_STRIDE + d4 * 4);
                acc0[j] += a0.x * kk4.x; acc0[j] += a0.y * kk4.y;
                acc0[j] += a0.z * kk4.z; acc0[j] += a0.w * kk4.w;
                acc1[j] += a1.x * kk4.x; acc1[j] += a1.y * kk4.y;
                acc1[j] += a1.z * kk4.z; acc1[j] += a1.w * kk4.w;
            }
        }

        // row-max partials
        float pm0 = acc0[0], pm1 = acc1[0];
#pragma unroll
        for (int j = 1; j < 8; j++) { pm0 = fmaxf(pm0, acc0[j]); pm1 = fmaxf(pm1, acc1[j]); }
        redm[r0 * RED_STRIDE + tcol] = pm0;
        redm[r1 * RED_STRIDE + tcol] = pm1;
        __syncthreads();

        float mt0 = redm[r0 * RED_STRIDE], mt1 = redm[r1 * RED_STRIDE];
#pragma unroll
        for (int jj = 1; jj < 8; jj++) {
            mt0 = fmaxf(mt0, redm[r0 * RED_STRIDE + jj]);
            mt1 = fmaxf(mt1, redm[r1 * RED_STRIDE + jj]);
        }
        float mn0 = fmaxf(mi0, mt0), mn1 = fmaxf(mi1, mt1);

        // P = exp(S - m), row-sum partials
        float s0 = 0.f, s1 = 0.f;
#pragma unroll
        for (int j = 0; j < 8; j++) {
            float p0v = __expf(acc0[j] - mn0);
            float p1v = __expf(acc1[j] - mn1);
            Ps[r0 * P_STRIDE + c0 + j] = p0v;
            Ps[r1 * P_STRIDE + c0 + j] = p1v;
            s0 += p0v; s1 += p1v;
        }
        reds[r0 * RED_STRIDE + tcol] = s0;
        reds[r1 * RED_STRIDE + tcol] = s1;
        __syncthreads();

        float ls0 = 0.f, ls1 = 0.f;
#pragma unroll
        for (int jj = 0; jj < 8; jj++) {
            ls0 += reds[r0 * RED_STRIDE + jj];
            ls1 += reds[r1 * RED_STRIDE + jj];
        }
        float al0 = __expf(mi0 - mn0), al1 = __expf(mi1 - mn1);
        li0 = li0 * al0 + ls0; mi0 = mn0;
        li1 = li1 * al1 + ls1; mi1 = mn1;

        // O = al*O + P @ V for my 16 columns
#pragma unroll
        for (int i = 0; i < 16; i++) { o0[i] *= al0; o1[i] *= al1; }
#pragma unroll 2
        for (int j = 0; j < 64; j++) {
            float p0v = Ps[r0 * P_STRIDE + j];
            float p1v = Ps[r1 * P_STRIDE + j];
            const float4* vp = (const float4*)(Vs + j * QKV_STRIDE + tcol * 16);
#pragma unroll
            for (int i4 = 0; i4 < 4; i4++) {
                float4 vv = vp[i4];
                o0[i4 * 4 + 0] += p0v * vv.x; o0[i4 * 4 + 1] += p0v * vv.y;
                o0[i4 * 4 + 2] += p0v * vv.z; o0[i4 * 4 + 3] += p0v * vv.w;
                o1[i4 * 4 + 0] += p1v * vv.x; o1[i4 * 4 + 1] += p1v * vv.y;
                o1[i4 * 4 + 2] += p1v * vv.z; o1[i4 * 4 + 3] += p1v * vv.w;
            }
        }
        __syncthreads();
    }

    float inv0 = 1.f / li0, inv1 = 1.f / li1;
    float* aob = ao + ((size_t)(b * SEQ + qt * 64)) * DIM + h * HD + tcol * 16;
#pragma unroll
    for (int i4 = 0; i4 < 4; i4++) {
        *(float4*)(aob + (size_t)r0 * DIM + i4 * 4) =
            make_float4(o0[i4*4+0]*inv0, o0[i4*4+1]*inv0, o0[i4*4+2]*inv0, o0[i4*4+3]*inv0);
        *(float4*)(aob + (size_t)r1 * DIM + i4 * 4) =
            make_float4(o1[i4*4+0]*inv1, o1[i4*4+1]*inv1, o1[i4*4+2]*inv1, o1[i4*4+3]*inv1);
    }
}

// -----------------------------------------------------------------------------
extern "C" void kernel_launch(void* const* d_in, const int* in_sizes, int n_in,
                              void* d_out, int out_size) {
    const float* x   = (const float*)d_in[0];
    const float* Wq  = (const float*)d_in[1];
    const float* Wk  = (const float*)d_in[2];
    const float* Wv  = (const float*)d_in[3];
    const float* Wo  = (const float*)d_in[4];
    const float* qnw = (const float*)d_in[5];
    const float* knw = (const float*)d_in[6];
    float* out = (float*)d_out;

    float *q, *k, *v, *ao;
    cudaGetSymbolAddress((void**)&q,  g_q);
    cudaGetSymbolAddress((void**)&k,  g_k);
    cudaGetSymbolAddress((void**)&v,  g_v);
    cudaGetSymbolAddress((void**)&ao, g_ao);

    const int flash_smem = FLASH_SMEM_FLOATS * (int)sizeof(float);
    cudaFuncSetAttribute(flash_attn, cudaFuncAttributeMaxDynamicSharedMemorySize,
                         flash_smem);

    dim3 gq(DIM / 128,   MROWS / 128);   // 16 x 32
    dim3 gk(KVDIM / 128, MROWS / 128);   // 4 x 32
    sgemm128<<<gq, 256>>>(x, Wq, q, DIM,   DIM);
    sgemm128<<<gk, 256>>>(x, Wk, k, KVDIM, DIM);
    sgemm128<<<gk, 256>>>(x, Wv, v, KVDIM, DIM);

    normrope<<<dim3(MROWS, NH + NKV), 128>>>(q, k, qnw, knw);

    flash_attn<<<dim3(SEQ / 64, NH, BATCH), 256, flash_smem>>>(q, k, v, ao);

    sgemm128<<<gq, 256>>>(ao, Wo, out, DIM, DIM);
}

// round 3
// speedup vs baseline: 1.0953x; 1.0953x over previous
#include <cuda_runtime.h>
#include <cuda_bf16.h>
#include <math.h>
#include <stdint.h>

#define BATCH 2
#define SEQ   2048
#define DIM   2048
#define NH    16
#define NKV   4
#define HD    128
#define MROWS (BATCH*SEQ)   /* 4096 */
#define KVDIM (NKV*HD)      /* 512  */

// tcgen05 is arch-SPECIFIC: only legal in the compute_103a pass.
#if defined(__CUDA_ARCH__) && defined(__CUDA_ARCH_FEAT_SM103_ALL)
#define HAVE_TC 1
#else
#define HAVE_TC 0
#endif

// ---------------- scratch --------------------------------------------------
__device__ float g_q [MROWS*DIM];
__device__ float g_k [MROWS*KVDIM];
__device__ float g_v [MROWS*KVDIM];
__device__ float g_ao[MROWS*DIM];

#if HAVE_TC
// ---------------- PTX helpers ----------------------------------------------
__device__ __forceinline__ uint32_t smem_u32(const void* p) {
    uint32_t a;
    asm("{ .reg .u64 t; cvta.to.shared.u64 t, %1; cvt.u32.u64 %0, t; }"
        : "=r"(a) : "l"(p));
    return a;
}
__device__ __forceinline__ uint32_t elect_one() {
    uint32_t pred;
    asm volatile("{ .reg .pred p; elect.sync _|p, 0xFFFFFFFF; selp.b32 %0,1,0,p; }"
                 : "=r"(pred));
    return pred;
}
#define MBARRIER_INIT(addr, cnt) \
    asm volatile("mbarrier.init.shared.b64 [%0], %1;" :: "r"(addr), "r"(cnt) : "memory")
#define MBARRIER_WAIT_PARITY(addr, par) do {                                   \
    uint32_t _m = (addr), _p = (par), _d;                                      \
    asm volatile("{ .reg .pred p; mbarrier.try_wait.parity.acquire.cta.shared::cta.b64 p, [%1], %2; selp.b32 %0,1,0,p; }" \
                 : "=r"(_d) : "r"(_m), "r"(_p) : "memory");                    \
    if (!_d) {                                                                 \
        asm volatile("{ .reg .pred P1; WL_%=: mbarrier.try_wait.parity.acquire.cta.shared::cta.b64 P1, [%0], %1, 0x989680; @P1 bra.uni WD_%=; bra.uni WL_%=; WD_%=: }" \
                     :: "r"(_m), "r"(_p) : "memory");                          \
    }                                                                          \
} while (0)
#define TCGEN05_ALLOC(res, n) \
    asm volatile("tcgen05.alloc.cta_group::1.sync.aligned.shared::cta.b32 [%0], %1;" \
                 :: "r"(res), "r"(n) : "memory")
#define TCGEN05_DEALLOC(t, n) \
    asm volatile("tcgen05.dealloc.cta_group::1.sync.aligned.b32 %0, %1;" :: "r"(t), "r"(n))
#define TCGEN05_RELINQ() \
    asm volatile("tcgen05.relinquish_alloc_permit.cta_group::1.sync.aligned;")
#define TCGEN05_COMMIT(mb) \
    asm volatile("tcgen05.commit.cta_group::1.mbarrier::arrive::one.shared::cluster.b64 [%0];" \
                 :: "r"(mb) : "memory")
#define TCGEN05_FENCE_AFTER() asm volatile("tcgen05.fence::after_thread_sync;" ::: "memory")
#define TCGEN05_WAIT_LD()     asm volatile("tcgen05.wait::ld.sync.aligned;" ::: "memory")
#define FENCE_ASYNC_SHARED()  asm volatile("fence.proxy.async.shared::cta;" ::: "memory")
#define TCGEN05_LD_X32(r, a)                                                   \
    asm volatile("tcgen05.ld.sync.aligned.32x32b.x32.b32 "                     \
        "{%0,%1,%2,%3,%4,%5,%6,%7,%8,%9,%10,%11,%12,%13,%14,%15,"              \
        "%16,%17,%18,%19,%20,%21,%22,%23,%24,%25,%26,%27,%28,%29,%30,%31}, [%32];" \
        : "=r"((r)[0]),"=r"((r)[1]),"=r"((r)[2]),"=r"((r)[3]),                 \
          "=r"((r)[4]),"=r"((r)[5]),"=r"((r)[6]),"=r"((r)[7]),                 \
          "=r"((r)[8]),"=r"((r)[9]),"=r"((r)[10]),"=r"((r)[11]),               \
          "=r"((r)[12]),"=r"((r)[13]),"=r"((r)[14]),"=r"((r)[15]),             \
          "=r"((r)[16]),"=r"((r)[17]),"=r"((r)[18]),"=r"((r)[19]),             \
          "=r"((r)[20]),"=r"((r)[21]),"=r"((r)[22]),"=r"((r)[23]),             \
          "=r"((r)[24]),"=r"((r)[25]),"=r"((r)[26]),"=r"((r)[27]),             \
          "=r"((r)[28]),"=r"((r)[29]),"=r"((r)[30]),"=r"((r)[31])              \
        : "r"(a))

// SW128 K-major descriptor: layout=2, version=1, SBO=64, LBO=1
__device__ __forceinline__ uint64_t make_desc(uint32_t addr) {
    return ( (uint64_t)2u << 61 ) | ( (uint64_t)1u << 46 )
         | ( (uint64_t)64u << 32 ) | ( (uint64_t)1u << 16 )
         | ( (uint64_t)(addr >> 4) & 0x3FFFu );
}
__device__ __forceinline__ void mma_f16_ss(uint32_t d, uint64_t a, uint64_t b,
                                           uint32_t idesc, uint32_t en) {
    asm volatile("{ .reg .pred p; setp.ne.u32 p, %5, 0;\n\t"
        "tcgen05.mma.cta_group::1.kind::f16 [%0], %1, %2, %3, {%4,%4,%4,%4}, p; }"
        :: "r"(d), "l"(a), "l"(b), "r"(idesc), "r"(0u), "r"(en) : "memory");
}
// idesc kind::f16: dtype=F32, atype=BF16, btype=BF16, N=128, M=128
#define GEMM_IDESC (0x490u | (16u << 17) | (8u << 24))
#endif // HAVE_TC

__device__ __forceinline__ uint32_t swz(uint32_t off) {
    return off ^ ((off >> 3) & 0x70u);
}

// ---------------- GEMM: C[M,N] = A[M,K] @ B[K,N], fp32 ---------------------
// grid (N/128, M/128), 256 threads, dynamic smem GEMM_SMEM.
// 103a pass: tcgen05 bf16x3.  base pass: classic FFMA 8x8 microtile fallback.
#define GEMM_SMEM (1024 + 1024 + 2*65536)

__global__ __launch_bounds__(256) void gemm_tc(const float* __restrict__ A,
                                               const float* __restrict__ B,
                                               float* __restrict__ C,
                                               int N, int K) {
#if HAVE_TC
    extern __shared__ char smem[];
    const uint32_t sb   = smem_u32(smem);
    const uint32_t base = (sb + 1023u) & ~1023u;
    const uint32_t hdr  = base;          // [0]=tmem ptr, [16],[24]=mbar0/1
    const uint32_t tile = base + 1024;
    char* tp = smem + (tile - sb);

    const int tid  = threadIdx.x;
    const int wid  = tid >> 5;
    const int lane = tid & 31;
    const int m0 = blockIdx.y * 128, n0 = blockIdx.x * 128;

    if (wid == 0) TCGEN05_ALLOC(hdr, 128);
    if (tid == 0) { MBARRIER_INIT(hdr + 16, 1); MBARRIER_INIT(hdr + 24, 1); }
    __syncthreads();
    uint32_t tmem;
    asm volatile("ld.shared.b32 %0, [%1];" : "=r"(tmem) : "r"(hdr));

    const int NC = K >> 6;     // 64-wide K chunks
    for (int c = 0; c < NC; c++) {
        const int buf  = c & 1;
        const int boff = buf * 65536;
        const int k0   = c << 6;

        if (c >= 2)
            MBARRIER_WAIT_PARITY(hdr + 16 + 8 * buf, (uint32_t)(((c >> 1) - 1) & 1));

        // A chunk: 128 m-rows x 64 k -> hi/lo bf16, K-major SW128 rows
#pragma unroll
        for (int i = 0; i < 8; i++) {
            int u  = tid + i * 256;
            int m  = u >> 4, k4 = u & 15;
            float4 a = *(const float4*)(A + (size_t)(m0 + m) * K + k0 + k4 * 4);
            __nv_bfloat16 h0 = __float2bfloat16(a.x);
            __nv_bfloat16 h1 = __float2bfloat16(a.y);
            __nv_bfloat16 h2 = __float2bfloat16(a.z);
            __nv_bfloat16 h3 = __float2bfloat16(a.w);
            __nv_bfloat16 l0 = __float2bfloat16(a.x - __bfloat162float(h0));
            __nv_bfloat16 l1 = __float2bfloat16(a.y - __bfloat162float(h1));
            __nv_bfloat16 l2 = __float2bfloat16(a.z - __bfloat162float(h2));
            __nv_bfloat16 l3 = __float2bfloat16(a.w - __bfloat162float(h3));
            uint32_t off = swz((uint32_t)(m * 128 + k4 * 8));
            __nv_bfloat162 hA(h0, h1), hB(h2, h3), lA(l0, l1), lB(l2, l3);
            *(uint2*)(tp + boff + off) = make_uint2(*(uint32_t*)&hA, *(uint32_t*)&hB);
            *(uint2*)(tp + boff + 16384 + off) = make_uint2(*(uint32_t*)&lA, *(uint32_t*)&lB);
        }

        // B chunk: B^T rows n (128) x 64 k.  B^T[n][k] = B[k][n].
#pragma unroll
        for (int i = 0; i < 8; i++) {
            int u = tid + i * 256;
            int n = u & 127, k4 = u >> 7;
            const float* bp = B + (size_t)(k0 + k4 * 4) * N + n0 + n;
            float b0 = bp[0], b1 = bp[N], b2 = bp[2 * (size_t)N], b3 = bp[3 * (size_t)N];
            __nv_bfloat16 h0 = __float2bfloat16(b0);
            __nv_bfloat16 h1 = __float2bfloat16(b1);
            __nv_bfloat16 h2 = __float2bfloat16(b2);
            __nv_bfloat16 h3 = __float2bfloat16(b3);
            __nv_bfloat16 l0 = __float2bfloat16(b0 - __bfloat162float(h0));
            __nv_bfloat16 l1 = __float2bfloat16(b1 - __bfloat162float(h1));
            __nv_bfloat16 l2 = __float2bfloat16(b2 - __bfloat162float(h2));
            __nv_bfloat16 l3 = __float2bfloat16(b3 - __bfloat162float(h3));
            uint32_t off = swz((uint32_t)(n * 128 + k4 * 8));
            __nv_bfloat162 hA(h0, h1), hB(h2, h3), lA(l0, l1), lB(l2, l3);
            *(uint2*)(tp + boff + 32768 + off) = make_uint2(*(uint32_t*)&hA, *(uint32_t*)&hB);
            *(uint2*)(tp + boff + 49152 + off) = make_uint2(*(uint32_t*)&lA, *(uint32_t*)&lB);
        }

        FENCE_ASYNC_SHARED();
        __syncthreads();

        if (wid == 0 && elect_one()) {
            uint64_t ah = make_desc(tile + boff);
            uint64_t al = make_desc(tile + boff + 16384);
            uint64_t bh = make_desc(tile + boff + 32768);
            uint64_t bl = make_desc(tile + boff + 49152);
#pragma unroll
            for (int s = 0; s < 4; s++) {       // K=16 per dispatch
                uint32_t en0 = (c == 0 && s == 0) ? 0u : 1u;
                mma_f16_ss(tmem, ah + s * 2, bh + s * 2, GEMM_IDESC, en0);
                mma_f16_ss(tmem, ah + s * 2, bl + s * 2, GEMM_IDESC, 1u);
                mma_f16_ss(tmem, al + s * 2, bh + s * 2, GEMM_IDESC, 1u);
            }
            TCGEN05_COMMIT(hdr + 16 + 8 * buf);
        }
    }

    MBARRIER_WAIT_PARITY(hdr + 16 + 8 * ((NC - 1) & 1),
                         (uint32_t)(((NC - 1) >> 1) & 1));
    TCGEN05_FENCE_AFTER();

    if (wid < 4) {
        float* crow = C + (size_t)(m0 + wid * 32 + lane) * N + n0;
#pragma unroll
        for (int g = 0; g < 4; g++) {
            uint32_t r[32];
            TCGEN05_LD_X32(r, tmem + g * 32);
            TCGEN05_WAIT_LD();
            float* f = (float*)r;
#pragma unroll
            for (int q4 = 0; q4 < 8; q4++)
                *(float4*)(crow + g * 32 + q4 * 4) =
                    make_float4(f[q4 * 4], f[q4 * 4 + 1], f[q4 * 4 + 2], f[q4 * 4 + 3]);
        }
    }
    __syncthreads();
    if (wid == 0) {
        TCGEN05_RELINQ();
        TCGEN05_DEALLOC(tmem, 128);
    }
#else
    // ---------------- FFMA fallback (base sm_103 pass) ----------------------
    __shared__ float As[8][128];
    __shared__ float Bs[8][128];
    const int bx = blockIdx.x, by = blockIdx.y;
    const int tid = threadIdx.x;
    const int tx = tid & 15, ty = tid >> 4;
    const int a_row = tid >> 1;
    const int a_col = (tid & 1) * 4;
    const int b_row = tid >> 5;
    const int b_col = (tid & 31) * 4;

    const float* Ab = A + (size_t)(by * 128) * K;
    const float* Bb = B + bx * 128;

    float acc[8][8];
#pragma unroll
    for (int i = 0; i < 8; i++)
#pragma unroll
        for (int j = 0; j < 8; j++) acc[i][j] = 0.f;

    for (int k0 = 0; k0 < K; k0 += 8) {
        float4 av = *(const float4*)(Ab + (size_t)a_row * K + k0 + a_col);
        As[a_col + 0][a_row] = av.x;
        As[a_col + 1][a_row] = av.y;
        As[a_col + 2][a_row] = av.z;
        As[a_col + 3][a_row] = av.w;
        *(float4*)&Bs[b_row][b_col] =
            *(const float4*)(Bb + (size_t)(k0 + b_row) * N + b_col);
        __syncthreads();
#pragma unroll
        for (int kk = 0; kk < 8; kk++) {
            float ar[8], br[8];
            *(float4*)(ar)     = *(const float4*)&As[kk][ty * 8];
            *(float4*)(ar + 4) = *(const float4*)&As[kk][ty * 8 + 4];
            *(float4*)(br)     = *(const float4*)&Bs[kk][tx * 8];
            *(float4*)(br + 4) = *(const float4*)&Bs[kk][tx * 8 + 4];
#pragma unroll
            for (int i = 0; i < 8; i++)
#pragma unroll
                for (int j = 0; j < 8; j++)
                    acc[i][j] += ar[i] * br[j];
        }
        __syncthreads();
    }

#pragma unroll
    for (int i = 0; i < 8; i++) {
        float* Crow = C + (size_t)(by * 128 + ty * 8 + i) * N + bx * 128 + tx * 8;
        *(float4*)Crow       = make_float4(acc[i][0], acc[i][1], acc[i][2], acc[i][3]);
        *(float4*)(Crow + 4) = make_float4(acc[i][4], acc[i][5], acc[i][6], acc[i][7]);
    }
#endif
}

// ---------------- fused per-head RMSNorm + RoPE (in place) -----------------
__global__ __launch_bounds__(128) void normrope(float* __restrict__ q,
                                                float* __restrict__ k,
                                                const float* __restrict__ qw,
                                                const float* __restrict__ kw) {
    const int row = blockIdx.x;
    const int hy  = blockIdx.y;
    const int d   = threadIdx.x;
    const int s   = row & (SEQ - 1);

    float* p;
    const float* w;
    if (hy < NH) { p = q + (size_t)row * DIM   + hy * HD;        w = qw; }
    else         { p = k + (size_t)row * KVDIM + (hy - NH) * HD; w = kw; }

    float x = p[d];
    float v2 = x * x;
#pragma unroll
    for (int off = 16; off > 0; off >>= 1)
        v2 += __shfl_xor_sync(0xffffffffu, v2, off);
    __shared__ float wsum[4];
    const int lane = d & 31, wid = d >> 5;
    if (lane == 0) wsum[wid] = v2;
    __syncthreads();
    float total = wsum[0] + wsum[1] + wsum[2] + wsum[3];
    float rn = rsqrtf(total * (1.0f / 128.0f) + 1e-6f);
    float nx = x * rn * w[d];

    __shared__ float sn[128];
    sn[d] = nx;
    __syncthreads();

    const int j = d & 63;
    float invf  = (float)exp(-9.210340371976184 * ((double)(2 * j) * (1.0 / 128.0)));
    float theta = (float)s * invf;
    double td = (double)theta;
    float c  = (float)cos(td);
    float si = (float)sin(td);
    float out = (d < 64) ? (nx * c - sn[d + 64] * si)
                         : (nx * c + sn[d - 64] * si);
    p[d] = out;
}

// ---------------- flash attention, fp32, BM=64 BN=64 D=128 -----------------
#define QKV_STRIDE 132
#define P_STRIDE   65
#define RED_STRIDE 9
#define FLASH_SMEM_FLOATS (3*64*QKV_STRIDE + 64*P_STRIDE + 2*64*RED_STRIDE)

__global__ __launch_bounds__(256) void flash_attn(const float* __restrict__ q,
                                                  const float* __restrict__ k,
                                                  const float* __restrict__ v,
                                                  float* __restrict__ ao) {
    extern __shared__ float sm[];
    float* Qs   = sm;
    float* Ks   = Qs + 64 * QKV_STRIDE;
    float* Vs   = Ks + 64 * QKV_STRIDE;
    float* Ps   = Vs + 64 * QKV_STRIDE;
    float* redm = Ps + 64 * P_STRIDE;
    float* reds = redm + 64 * RED_STRIDE;

    const int qt  = blockIdx.x;
    const int h   = blockIdx.y;
    const int b   = blockIdx.z;
    const int kv  = h >> 2;
    const int tid = threadIdx.x;

    const int r0   = tid & 31;
    const int r1   = r0 + 32;
    const int tcol = tid >> 5;
    const int c0   = tcol * 8;

    const float scale = 0.08838834764831843f;

    const float* qbase = q + ((size_t)(b * SEQ + qt * 64)) * DIM + h * HD;
#pragma unroll
    for (int i = 0; i < 8; i++) {
        int lin = tid + i * 256;
        int m = lin >> 5, d4 = lin & 31;
        float4 t = *(const float4*)(qbase + (size_t)m * DIM + d4 * 4);
        t.x *= scale; t.y *= scale; t.z *= scale; t.w *= scale;
        *(float4*)(Qs + m * QKV_STRIDE + d4 * 4) = t;
    }

    float mi0 = -1e30f, mi1 = -1e30f, li0 = 0.f, li1 = 0.f;
    float o0[16], o1[16];
#pragma unroll
    for (int i = 0; i < 16; i++) { o0[i] = 0.f; o1[i] = 0.f; }

    const float* kbase = k + (size_t)(b * SEQ) * KVDIM + kv * HD;
    const float* vbase = v + (size_t)(b * SEQ) * KVDIM + kv * HD;

    for (int kt = 0; kt < SEQ / 64; kt++) {
        const float* kb = kbase + (size_t)(kt * 64) * KVDIM;
        const float* vb = vbase + (size_t)(kt * 64) * KVDIM;
#pragma unroll
        for (int i = 0; i < 8; i++) {
            int lin = tid + i * 256;
            int n = lin >> 5, d4 = lin & 31;
            *(float4*)(Ks + n * QKV_STRIDE + d4 * 4) =
                *(const float4*)(kb + (size_t)n * KVDIM + d4 * 4);
            *(float4*)(Vs + n * QKV_STRIDE + d4 * 4) =
                *(const float4*)(vb + (size_t)n * KVDIM + d4 * 4);
        }
        __syncthreads();

        float acc0[8], acc1[8];
#pragma unroll
        for (int j = 0; j < 8; j++) { acc0[j] = 0.f; acc1[j] = 0.f; }
        const float4* q0p = (const float4*)(Qs + r0 * QKV_STRIDE);
        const float4* q1p = (const float4*)(Qs + r1 * QKV_STRIDE);
#pragma unroll 4
        for (int d4 = 0; d4 < 32; d4++) {
            float4 a0 = q0p[d4], a1 = q1p[d4];
#pragma unroll
            for (int j = 0; j < 8; j++) {
                float4 kk4 = *(const float4*)(Ks + (c0 + j) * QKV_STRIDE + d4 * 4);
                acc0[j] += a0.x * kk4.x; acc0[j] += a0.y * kk4.y;
                acc0[j] += a0.z * kk4.z; acc0[j] += a0.w * kk4.w;
                acc1[j] += a1.x * kk4.x; acc1[j] += a1.y * kk4.y;
                acc1[j] += a1.z * kk4.z; acc1[j] += a1.w * kk4.w;
            }
        }

        float pm0 = acc0[0], pm1 = acc1[0];
#pragma unroll
        for (int j = 1; j < 8; j++) { pm0 = fmaxf(pm0, acc0[j]); pm1 = fmaxf(pm1, acc1[j]); }
        redm[r0 * RED_STRIDE + tcol] = pm0;
        redm[r1 * RED_STRIDE + tcol] = pm1;
        __syncthreads();

        float mt0 = redm[r0 * RED_STRIDE], mt1 = redm[r1 * RED_STRIDE];
#pragma unroll
        for (int jj = 1; jj < 8; jj++) {
            mt0 = fmaxf(mt0, redm[r0 * RED_STRIDE + jj]);
            mt1 = fmaxf(mt1, redm[r1 * RED_STRIDE + jj]);
        }
        float mn0 = fmaxf(mi0, mt0), mn1 = fmaxf(mi1, mt1);

        float s0 = 0.f, s1 = 0.f;
#pragma unroll
        for (int j = 0; j < 8; j++) {
            float p0v = __expf(acc0[j] - mn0);
            float p1v = __expf(acc1[j] - mn1);
            Ps[r0 * P_STRIDE + c0 + j] = p0v;
            Ps[r1 * P_STRIDE + c0 + j] = p1v;
            s0 += p0v; s1 += p1v;
        }
        reds[r0 * RED_STRIDE + tcol] = s0;
        reds[r1 * RED_STRIDE + tcol] = s1;
        __syncthreads();

        float ls0 = 0.f, ls1 = 0.f;
#pragma unroll
        for (int jj = 0; jj < 8; jj++) {
            ls0 += reds[r0 * RED_STRIDE + jj];
            ls1 += reds[r1 * RED_STRIDE + jj];
        }
        float al0 = __expf(mi0 - mn0), al1 = __expf(mi1 - mn1);
        li0 = li0 * al0 + ls0; mi0 = mn0;
        li1 = li1 * al1 + ls1; mi1 = mn1;

#pragma unroll
        for (int i = 0; i < 16; i++) { o0[i] *= al0; o1[i] *= al1; }
#pragma unroll 2
        for (int j = 0; j < 64; j++) {
            float p0v = Ps[r0 * P_STRIDE + j];
            float p1v = Ps[r1 * P_STRIDE + j];
            const float4* vp = (const float4*)(Vs + j * QKV_STRIDE + tcol * 16);
#pragma unroll
            for (int i4 = 0; i4 < 4; i4++) {
                float4 vv = vp[i4];
                o0[i4 * 4 + 0] += p0v * vv.x; o0[i4 * 4 + 1] += p0v * vv.y;
                o0[i4 * 4 + 2] += p0v * vv.z; o0[i4 * 4 + 3] += p0v * vv.w;
                o1[i4 * 4 + 0] += p1v * vv.x; o1[i4 * 4 + 1] += p1v * vv.y;
                o1[i4 * 4 + 2] += p1v * vv.z; o1[i4 * 4 + 3] += p1v * vv.w;
            }
        }
        __syncthreads();
    }

    float inv0 = 1.f / li0, inv1 = 1.f / li1;
    float* aob = ao + ((size_t)(b * SEQ + qt * 64)) * DIM + h * HD + tcol * 16;
#pragma unroll
    for (int i4 = 0; i4 < 4; i4++) {
        *(float4*)(aob + (size_t)r0 * DIM + i4 * 4) =
            make_float4(o0[i4*4+0]*inv0, o0[i4*4+1]*inv0, o0[i4*4+2]*inv0, o0[i4*4+3]*inv0);
        *(float4*)(aob + (size_t)r1 * DIM + i4 * 4) =
            make_float4(o1[i4*4+0]*inv1, o1[i4*4+1]*inv1, o1[i4*4+2]*inv1, o1[i4*4+3]*inv1);
    }
}

// -----------------------------------------------------------------------------
extern "C" void kernel_launch(void* const* d_in, const int* in_sizes, int n_in,
                              void* d_out, int out_size) {
    const float* x   = (const float*)d_in[0];
    const float* Wq  = (const float*)d_in[1];
    const float* Wk  = (const float*)d_in[2];
    const float* Wv  = (const float*)d_in[3];
    const float* Wo  = (const float*)d_in[4];
    const float* qnw = (const float*)d_in[5];
    const float* knw = (const float*)d_in[6];
    float* out = (float*)d_out;

    float *q, *k, *v, *ao;
    cudaGetSymbolAddress((void**)&q,  g_q);
    cudaGetSymbolAddress((void**)&k,  g_k);
    cudaGetSymbolAddress((void**)&v,  g_v);
    cudaGetSymbolAddress((void**)&ao, g_ao);

    const int flash_smem = FLASH_SMEM_FLOATS * (int)sizeof(float);
    cudaFuncSetAttribute(flash_attn, cudaFuncAttributeMaxDynamicSharedMemorySize,
                         flash_smem);
    cudaFuncSetAttribute(gemm_tc, cudaFuncAttributeMaxDynamicSharedMemorySize,
                         GEMM_SMEM);

    dim3 gq(DIM / 128,   MROWS / 128);   // 16 x 32
    dim3 gk(KVDIM / 128, MROWS / 128);   // 4 x 32
    gemm_tc<<<gq, 256, GEMM_SMEM>>>(x, Wq, q, DIM,   DIM);
    gemm_tc<<<gk, 256, GEMM_SMEM>>>(x, Wk, k, KVDIM, DIM);
    gemm_tc<<<gk, 256, GEMM_SMEM>>>(x, Wv, v, KVDIM, DIM);

    normrope<<<dim3(MROWS, NH + NKV), 128>>>(q, k, qnw, knw);

    flash_attn<<<dim3(SEQ / 64, NH, BATCH), 256, flash_smem>>>(q, k, v, ao);

    gemm_tc<<<gq, 256, GEMM_SMEM>>>(ao, Wo, out, DIM, DIM);
}